// round 15
// baseline (speedup 1.0000x reference)
#include <cuda_runtime.h>
#include <cuda_fp16.h>
#include <cstdint>

#define N_NODES 100000
#define N_EDGES 3200000
#define F_IN 64
#define HID 20
#define ROWH 32                             // halves per padded row (64B)
#define N_GRAPHS 128
#define N_CLASSES 10
#define EPS_NORM 1e-12f
#define SCAN_B ((N_NODES + 1023) / 1024)    // 98

// ---------------- scratch (device globals) ---------------------------------
__device__ __align__(128) __half g_bufA[N_NODES * ROWH];  // fp16 rows, 64B stride
__device__ __align__(128) __half g_bufB[N_NODES * ROWH];
__device__ __align__(16) float g_agg[N_NODES * HID];
__device__ __align__(16) int g_edge_raw[2 * N_EDGES];     // int2 (s,w) or int (s)
__device__ int g_deg[N_NODES];
__device__ int g_rowptr[N_NODES + 1];
__device__ int g_cursor[N_NODES];
__device__ int g_bsum[SCAN_B];
__device__ int g_boff[SCAN_B];
__device__ int g_scnt;
__device__ int g_sflag;
__device__ float g_pmax[N_GRAPHS * HID];
__device__ float g_psum[N_GRAPHS * HID];
__device__ float g_cnt[N_GRAPHS];
__device__ int   g_is64;
__device__ int   g_wuni;                                  // 1 if all weights == 1.0f

// ---------------- init: dtype probe + zero deg/pool/scan state --------------
__global__ void k_init(const void* __restrict__ ei) {
    int i = blockIdx.x * blockDim.x + threadIdx.x;
    if (i == 0) {
        const long long* p = (const long long*)ei;
        bool ok = true;
        #pragma unroll
        for (int q = 0; q < 16; q++) {
            long long v = p[q];
            if (v < 0 || v >= (long long)N_NODES) ok = false;
        }
        g_is64 = ok ? 1 : 0;
        g_wuni = 1;
        g_scnt = 0;
        g_sflag = 0;
    }
    if (i < N_NODES) g_deg[i] = 0;
    if (i < N_GRAPHS * HID) { g_pmax[i] = 0.0f; g_psum[i] = 0.0f; }
    if (i < N_GRAPHS) g_cnt[i] = 0.0f;
}

// ---------------- fused layer-1 GEMM + degree histogram ---------------------
// Independent work in one kernel: grid-strided hist over edges + 1 node GEMM
// per thread. Mixes mem-heavy atomics with FMA-heavy gemm.
__global__ __launch_bounds__(256) void k_gemm_hist(const float* __restrict__ x,
                                                   const float* __restrict__ W,
                                                   const void* __restrict__ ei,
                                                   const float* __restrict__ w) {
    __shared__ float sW[F_IN * HID];   // 5.1 KB
    int tid = threadIdx.x;
    for (int i = tid; i < F_IN * HID; i += 256) sW[i] = W[i];

    // --- histogram part (grid-strided over edges) ---
    int gsz = gridDim.x * 256;
    int gt = blockIdx.x * 256 + tid;
    bool is64 = (g_is64 != 0);
    bool wbad = false;
    for (int e = gt; e < N_EDGES; e += gsz) {
        int d;
        if (is64) d = (int)((const long long*)ei)[N_EDGES + e];
        else      d = ((const int*)ei)[N_EDGES + e];
        atomicAdd(&g_deg[d], 1);
        if (w[e] != 1.0f) wbad = true;
    }
    if (wbad) g_wuni = 0;   // benign race: all writers store 0

    __syncthreads();

    // --- GEMM part ---
    int n = blockIdx.x * 256 + tid;
    if (n >= N_NODES) return;

    const float4* xr = (const float4*)(x + (size_t)n * F_IN);

    float acc[HID];
    #pragma unroll
    for (int j = 0; j < HID; j++) acc[j] = 0.0f;

    #pragma unroll
    for (int c = 0; c < 4; c++) {
        float4 xv[4];
        #pragma unroll
        for (int q = 0; q < 4; q++) xv[q] = __ldg(xr + c * 4 + q);
        const float* xs = (const float*)xv;
        #pragma unroll
        for (int kk = 0; kk < 16; kk++) {
            int k = c * 16 + kk;
            float xk = xs[kk];
            const float4* wr = (const float4*)&sW[k * HID];
            #pragma unroll
            for (int q = 0; q < 5; q++) {
                float4 wv = wr[q];
                acc[4 * q + 0] += xk * wv.x;
                acc[4 * q + 1] += xk * wv.y;
                acc[4 * q + 2] += xk * wv.z;
                acc[4 * q + 3] += xk * wv.w;
            }
        }
    }
    unsigned hp[16];
    #pragma unroll
    for (int q = 0; q < 10; q++) {
        __half2 h = __floats2half2_rn(acc[2 * q], acc[2 * q + 1]);
        hp[q] = *(unsigned*)&h;
    }
    #pragma unroll
    for (int q = 10; q < 16; q++) hp[q] = 0u;
    uint4* op = (uint4*)(g_bufA + (size_t)n * ROWH);
    op[0] = make_uint4(hp[0], hp[1], hp[2], hp[3]);
    op[1] = make_uint4(hp[4], hp[5], hp[6], hp[7]);
    op[2] = make_uint4(hp[8], hp[9], hp[10], hp[11]);
    op[3] = make_uint4(hp[12], hp[13], hp[14], hp[15]);
}

// ---------------- single-kernel exclusive scan (98 blocks, all resident) ----
__global__ __launch_bounds__(1024) void k_scan() {
    __shared__ int s[1024];
    int t = threadIdx.x;
    int i = blockIdx.x * 1024 + t;
    int v = (i < N_NODES) ? g_deg[i] : 0;
    s[t] = v;
    __syncthreads();
    #pragma unroll
    for (int off = 1; off < 1024; off <<= 1) {
        int u = (t >= off) ? s[t - off] : 0;
        __syncthreads();
        s[t] += u;
        __syncthreads();
    }
    int incl = s[t];

    if (t == 1023) {
        g_bsum[blockIdx.x] = s[1023];
        __threadfence();
        int done = atomicAdd(&g_scnt, 1);
        if (done == gridDim.x - 1) {            // last arriver scans block sums
            int run = 0;
            for (int b = 0; b < SCAN_B; b++) {
                g_boff[b] = run;
                run += g_bsum[b];
            }
            g_rowptr[N_NODES] = run;
            __threadfence();
            atomicExch(&g_sflag, 1);
        }
    }
    if (t == 0) {
        while (atomicAdd(&g_sflag, 0) == 0) { }
    }
    __syncthreads();
    __threadfence();

    if (i < N_NODES) {
        int ex = incl - v + g_boff[blockIdx.x];
        g_rowptr[i] = ex;
        g_cursor[i] = ex;
    }
}

__global__ void k_fill(const void* __restrict__ ei, const float* __restrict__ w) {
    int e = blockIdx.x * blockDim.x + threadIdx.x;
    if (e >= N_EDGES) return;
    int s, d;
    if (g_is64) {
        const long long* p = (const long long*)ei;
        s = (int)p[e]; d = (int)p[N_EDGES + e];
    } else {
        const int* p = (const int*)ei;
        s = p[e]; d = p[N_EDGES + e];
    }
    int pos = atomicAdd(&g_cursor[d], 1);
    if (g_wuni) {
        g_edge_raw[pos] = s;                          // src only, 4B
    } else {
        ((int2*)g_edge_raw)[pos] = make_int2(s, __float_as_int(w[e]));
    }
}

// ---------------- helpers ---------------------------------------------------
__device__ __forceinline__ void store_row_fp16(__half* base, int n, const float* o) {
    unsigned hp[16];
    #pragma unroll
    for (int q = 0; q < 10; q++) {
        __half2 h = __floats2half2_rn(o[2 * q], o[2 * q + 1]);
        hp[q] = *(unsigned*)&h;
    }
    #pragma unroll
    for (int q = 10; q < 16; q++) hp[q] = 0u;
    uint4* op = (uint4*)(base + (size_t)n * ROWH);
    op[0] = make_uint4(hp[0], hp[1], hp[2], hp[3]);
    op[1] = make_uint4(hp[4], hp[5], hp[6], hp[7]);
    op[2] = make_uint4(hp[8], hp[9], hp[10], hp[11]);
    op[3] = make_uint4(hp[12], hp[13], hp[14], hp[15]);
}

// ---------------- aggregation: 3-lane cooperative gather, 2-deep pipeline ---
// 10 groups x 3 lanes per warp; lane role r loads bytes [16r,16r+16) of the
// 64B-aligned row. Unroll x2: both edges' index loads issue before both row
// loads -> 2 row fetches in flight per group (breaks the dependent chain).
// mode selects input: 0,2 -> bufA ; 1 -> bufB.  Output: g_agg (fp32).
#define AW 8
__global__ __launch_bounds__(AW * 32) void k_agg(int mode) {
    __shared__ float red[AW][32][9];   // [warp][lane][8 feats + pad]
    int tid = threadIdx.x;
    int wid = tid >> 5, lane = tid & 31;
    int n = blockIdx.x * AW + wid;
    if (n >= N_NODES) return;

    const char* in = (const char*)((mode == 1) ? g_bufB : g_bufA);
    bool uni = (g_wuni != 0);
    int rs = __ldg(&g_rowptr[n]);
    int re = __ldg(&g_rowptr[n + 1]);

    int grp  = lane / 3;           // 0..9 valid; 10 for lanes 30,31
    int role = lane - grp * 3;     // 0..2
    bool active = grp < 10;

    float acc[8];
    #pragma unroll
    for (int j = 0; j < 8; j++) acc[j] = 0.0f;

    if (active) {
        if (uni) {
            const int* ep = g_edge_raw;
            for (int e = rs + grp; e < re; e += 20) {
                int e2 = e + 10;
                bool h2 = e2 < re;
                int sA = __ldg(ep + e);
                int sB = h2 ? __ldg(ep + e2) : sA;
                uint4 vA = __ldg((const uint4*)(in + (size_t)sA * 64) + role);
                uint4 vB = __ldg((const uint4*)(in + (size_t)sB * 64) + role);
                float wB = h2 ? 1.0f : 0.0f;
                unsigned ha[4] = {vA.x, vA.y, vA.z, vA.w};
                unsigned hb[4] = {vB.x, vB.y, vB.z, vB.w};
                #pragma unroll
                for (int q = 0; q < 4; q++) {
                    float2 fa = __half22float2(*(__half2*)&ha[q]);
                    float2 fb = __half22float2(*(__half2*)&hb[q]);
                    acc[2 * q + 0] += fa.x + fb.x * wB;
                    acc[2 * q + 1] += fa.y + fb.y * wB;
                }
            }
        } else {
            const int2* ep = (const int2*)g_edge_raw;
            for (int e = rs + grp; e < re; e += 20) {
                int e2 = e + 10;
                bool h2 = e2 < re;
                int2 pA = __ldg(ep + e);
                int2 pB = h2 ? __ldg(ep + e2) : pA;
                float wA = __int_as_float(pA.y);
                float wB = h2 ? __int_as_float(pB.y) : 0.0f;
                uint4 vA = __ldg((const uint4*)(in + (size_t)pA.x * 64) + role);
                uint4 vB = __ldg((const uint4*)(in + (size_t)pB.x * 64) + role);
                unsigned ha[4] = {vA.x, vA.y, vA.z, vA.w};
                unsigned hb[4] = {vB.x, vB.y, vB.z, vB.w};
                #pragma unroll
                for (int q = 0; q < 4; q++) {
                    float2 fa = __half22float2(*(__half2*)&ha[q]);
                    float2 fb = __half22float2(*(__half2*)&hb[q]);
                    acc[2 * q + 0] += fa.x * wA + fb.x * wB;
                    acc[2 * q + 1] += fa.y * wA + fb.y * wB;
                }
            }
        }
    }

    // reduction: feature f = 8*role + j lives in lanes {3g + role}, g = 0..9
    float (*rp)[9] = red[wid];
    #pragma unroll
    for (int j = 0; j < 8; j++) rp[lane][j] = acc[j];
    __syncwarp();

    if (lane < HID) {
        int r = lane >> 3, j = lane & 7;
        float s = 0.0f;
        #pragma unroll
        for (int g = 0; g < 10; g++) s += rp[3 * g + r][j];
        g_agg[(size_t)n * HID + lane] = s;               // coalesced 80B per warp
    }
}

// ---------------- node MLP; mode 2 fuses global pooling ---------------------
// mode: 0 -> bufB(fp16), 1 -> bufA(fp16), 2 -> pooled atomics (no row output)
__global__ __launch_bounds__(128) void k_mlp(const float* __restrict__ ba,
                                             const float* __restrict__ Wb,
                                             const float* __restrict__ bb,
                                             const float* __restrict__ Wn,
                                             const void* __restrict__ batch_v,
                                             int mode) {
    __shared__ float sWb[HID * HID], sWn[HID * HID], sba[HID], sbb[HID];
    int tid = threadIdx.x;
    for (int i = tid; i < HID * HID; i += 128) {
        sWb[i] = Wb[i];
        sWn[i] = Wn ? Wn[i] : 0.0f;
    }
    if (tid < HID) { sba[tid] = ba[tid]; sbb[tid] = bb[tid]; }
    __syncthreads();
    int n = blockIdx.x * 128 + tid;
    bool valid = n < N_NODES;
    if (!valid && mode != 2) return;

    float z[HID];
    if (valid) {
        float4 t[5];
        const float4* ag = (const float4*)(g_agg + (size_t)n * HID);
        #pragma unroll
        for (int i = 0; i < 5; i++) t[i] = __ldg(ag + i);
        float* zt = (float*)t;

        #pragma unroll
        for (int k = 0; k < HID; k++) z[k] = fmaxf(zt[k] + sba[k], 0.0f);

        float z2[HID];
        #pragma unroll
        for (int j = 0; j < HID; j++) {
            float a = sbb[j];
            #pragma unroll
            for (int k = 0; k < HID; k++) a += z[k] * sWb[k * HID + j];
            z2[j] = fmaxf(a, 0.0f);
        }

        float ss = 0.0f;
        #pragma unroll
        for (int k = 0; k < HID; k++) ss += z2[k] * z2[k];
        float inv = 1.0f / fmaxf(sqrtf(ss), EPS_NORM);
        #pragma unroll
        for (int k = 0; k < HID; k++) z[k] = fmaxf(z2[k] * inv, 0.0f);  // h
    } else {
        #pragma unroll
        for (int k = 0; k < HID; k++) z[k] = 0.0f;
    }

    if (mode != 2) {
        float o[HID];
        #pragma unroll
        for (int j = 0; j < HID; j++) {
            float a = 0.0f;
            #pragma unroll
            for (int k = 0; k < HID; k++) a += z[k] * sWn[k * HID + j];
            o[j] = a;
        }
        store_row_fp16((mode == 0) ? g_bufB : g_bufA, n, o);
        return;
    }

    // ---- fused global max/mean pooling (batch is sorted by graph) ----
    int g = -1;
    if (valid) {
        if (g_is64) g = (int)((const long long*)batch_v)[n];
        else        g = ((const int*)batch_v)[n];
    }
    const unsigned m = 0xffffffffu;
    int g0 = __shfl_sync(m, g, 0);
    bool uni = __all_sync(m, g == g0) && (g0 >= 0);
    int lane = tid & 31;

    if (uni) {
        #pragma unroll
        for (int f = 0; f < HID; f++) {
            float s = z[f], mx = z[f];
            #pragma unroll
            for (int off = 16; off > 0; off >>= 1) {
                s += __shfl_xor_sync(m, s, off);
                mx = fmaxf(mx, __shfl_xor_sync(m, mx, off));
            }
            if (lane == 0) {
                atomicAdd(&g_psum[g0 * HID + f], s);
                atomicMax((int*)&g_pmax[g0 * HID + f], __float_as_int(mx));  // h >= 0
            }
        }
        if (lane == 0) atomicAdd(&g_cnt[g0], 32.0f);
    } else if (valid) {
        #pragma unroll
        for (int f = 0; f < HID; f++) {
            atomicAdd(&g_psum[g * HID + f], z[f]);
            atomicMax((int*)&g_pmax[g * HID + f], __float_as_int(z[f]));
        }
        atomicAdd(&g_cnt[g], 1.0f);
    }
}

__global__ void k_final(const float* __restrict__ Wlin, const float* __restrict__ blin,
                        float* __restrict__ out) {
    int idx = blockIdx.x * blockDim.x + threadIdx.x;
    if (idx >= N_GRAPHS * N_CLASSES) return;
    int gph = idx / N_CLASSES, c = idx % N_CLASSES;
    float cnt = g_cnt[gph];
    float icnt = 1.0f / fmaxf(cnt, 1.0f);
    float acc = __ldg(blin + c);
    #pragma unroll
    for (int k = 0; k < HID; k++) {
        float mx = (cnt > 0.0f) ? g_pmax[gph * HID + k] : 0.0f;
        float mean = g_psum[gph * HID + k] * icnt;
        acc += mx * __ldg(Wlin + k * N_CLASSES + c)
             + mean * __ldg(Wlin + (HID + k) * N_CLASSES + c);
    }
    out[idx] = acc;
}

// ---------------- launch ----------------------------------------------------
extern "C" void kernel_launch(void* const* d_in, const int* in_sizes, int n_in,
                              void* d_out, int out_size) {
    const float* x    = (const float*)d_in[0];
    const void*  ei   = d_in[1];
    const void*  batch= d_in[2];
    const float* ew   = (const float*)d_in[3];
    const float* W1a  = (const float*)d_in[4];
    const float* b1a  = (const float*)d_in[5];
    const float* W1b  = (const float*)d_in[6];
    const float* b1b  = (const float*)d_in[7];
    const float* W2a  = (const float*)d_in[8];
    const float* b2a  = (const float*)d_in[9];
    const float* W2b  = (const float*)d_in[10];
    const float* b2b  = (const float*)d_in[11];
    const float* W3a  = (const float*)d_in[12];
    const float* b3a  = (const float*)d_in[13];
    const float* W3b  = (const float*)d_in[14];
    const float* b3b  = (const float*)d_in[15];
    const float* Wlin = (const float*)d_in[16];
    const float* blin = (const float*)d_in[17];
    float* out = (float*)d_out;

    const int eg = (N_EDGES + 255) / 256;
    const int ng = (N_NODES + 255) / 256;
    const int ag = (N_NODES + AW - 1) / AW;
    const int mg = (N_NODES + 127) / 128;
    const int gg = (N_NODES + 255) / 256;

    k_init<<<ng, 256>>>(ei);
    k_gemm_hist<<<gg, 256>>>(x, W1a, ei, ew);
    k_scan<<<SCAN_B, 1024>>>();
    k_fill<<<eg, 256>>>(ei, ew);

    // three layers: pipelined agg + node MLP; layer 3 fuses pooling
    k_agg<<<ag, AW * 32>>>(0);  k_mlp<<<mg, 128>>>(b1a, W1b, b1b, W2a, nullptr, 0);
    k_agg<<<ag, AW * 32>>>(1);  k_mlp<<<mg, 128>>>(b2a, W2b, b2b, W3a, nullptr, 1);
    k_agg<<<ag, AW * 32>>>(2);  k_mlp<<<mg, 128>>>(b3a, W3b, b3b, nullptr, batch, 2);

    k_final<<<2, 640>>>(Wlin, blin, out);
}

// round 16
// speedup vs baseline: 1.0419x; 1.0419x over previous
#include <cuda_runtime.h>
#include <cuda_fp16.h>
#include <cstdint>

#define N_NODES 100000
#define N_EDGES 3200000
#define F_IN 64
#define HID 20
#define ROWH 32                             // halves per fp16 row (64B)
#define QW 8                                // words per quant row (32B)
#define N_GRAPHS 128
#define N_CLASSES 10
#define EPS_NORM 1e-12f
#define SCAN_B ((N_NODES + 1023) / 1024)    // 98

// ---------------- scratch (device globals) ---------------------------------
__device__ __align__(128) __half g_bufA[N_NODES * ROWH];   // layer-1 fp16 rows
__device__ __align__(128) unsigned g_bufQ1[N_NODES * QW];  // 12-bit rows, 32B
__device__ __align__(128) unsigned g_bufQ2[N_NODES * QW];
__device__ __align__(16) float g_agg[N_NODES * HID];
__device__ __align__(16) int g_edge_raw[2 * N_EDGES];      // int2 (s,w) or int (s)
__device__ int g_deg[N_NODES];
__device__ int g_rowptr[N_NODES + 1];
__device__ int g_cursor[N_NODES];
__device__ int g_bsum[SCAN_B];
__device__ int g_boff[SCAN_B];
__device__ float g_qstep[2];                // dequant step per quant layer
__device__ float g_pmax[N_GRAPHS * HID];
__device__ float g_psum[N_GRAPHS * HID];
__device__ float g_cnt[N_GRAPHS];
__device__ int   g_is64;
__device__ int   g_wuni;                    // 1 if all weights == 1.0f

// ---------------- init ------------------------------------------------------
__global__ void k_init(const void* __restrict__ ei) {
    int i = blockIdx.x * blockDim.x + threadIdx.x;
    if (i == 0) {
        const long long* p = (const long long*)ei;
        bool ok = true;
        #pragma unroll
        for (int q = 0; q < 16; q++) {
            long long v = p[q];
            if (v < 0 || v >= (long long)N_NODES) ok = false;
        }
        g_is64 = ok ? 1 : 0;
        g_wuni = 1;
    }
    if (i < N_NODES) g_deg[i] = 0;
    if (i < N_GRAPHS * HID) { g_pmax[i] = 0.0f; g_psum[i] = 0.0f; }
    if (i < N_GRAPHS) g_cnt[i] = 0.0f;
}

// ---------------- CSR build -------------------------------------------------
__global__ void k_hist(const void* __restrict__ ei, const float* __restrict__ w) {
    int e = blockIdx.x * blockDim.x + threadIdx.x;
    if (e >= N_EDGES) return;
    int d;
    if (g_is64) d = (int)((const long long*)ei)[N_EDGES + e];
    else        d = ((const int*)ei)[N_EDGES + e];
    atomicAdd(&g_deg[d], 1);
    if (w[e] != 1.0f) g_wuni = 0;
}

__global__ void k_scan1() {
    __shared__ int s[1024];
    int t = threadIdx.x;
    int i = blockIdx.x * 1024 + t;
    s[t] = (i < N_NODES) ? g_deg[i] : 0;
    __syncthreads();
    #pragma unroll
    for (int off = 512; off > 0; off >>= 1) {
        if (t < off) s[t] += s[t + off];
        __syncthreads();
    }
    if (t == 0) g_bsum[blockIdx.x] = s[0];
}

__global__ void k_scan2() {
    if (threadIdx.x == 0) {
        int run = 0;
        for (int i = 0; i < SCAN_B; i++) {
            g_boff[i] = run;
            run += g_bsum[i];
        }
        g_rowptr[N_NODES] = run;
    }
}

__global__ void k_scan3() {
    __shared__ int s[1024];
    int t = threadIdx.x;
    int i = blockIdx.x * 1024 + t;
    int v = (i < N_NODES) ? g_deg[i] : 0;
    s[t] = v;
    __syncthreads();
    #pragma unroll
    for (int off = 1; off < 1024; off <<= 1) {
        int u = (t >= off) ? s[t - off] : 0;
        __syncthreads();
        s[t] += u;
        __syncthreads();
    }
    if (i < N_NODES) {
        int ex = s[t] - v + g_boff[blockIdx.x];
        g_rowptr[i] = ex;
        g_cursor[i] = ex;
    }
}

__global__ void k_fill(const void* __restrict__ ei, const float* __restrict__ w) {
    int e = blockIdx.x * blockDim.x + threadIdx.x;
    if (e >= N_EDGES) return;
    int s, d;
    if (g_is64) {
        const long long* p = (const long long*)ei;
        s = (int)p[e]; d = (int)p[N_EDGES + e];
    } else {
        const int* p = (const int*)ei;
        s = p[e]; d = p[N_EDGES + e];
    }
    int pos = atomicAdd(&g_cursor[d], 1);
    if (g_wuni) {
        g_edge_raw[pos] = s;
    } else {
        ((int2*)g_edge_raw)[pos] = make_int2(s, __float_as_int(w[e]));
    }
}

// ---------------- layer-1 GEMM: bufA = fp16(x @ W1a) ------------------------
__global__ __launch_bounds__(256) void k_gemm_in(const float* __restrict__ x,
                                                 const float* __restrict__ W) {
    __shared__ float sW[F_IN * HID];
    int tid = threadIdx.x;
    for (int i = tid; i < F_IN * HID; i += 256) sW[i] = W[i];
    __syncthreads();
    int n = blockIdx.x * 256 + tid;
    if (n >= N_NODES) return;

    const float4* xr = (const float4*)(x + (size_t)n * F_IN);
    float acc[HID];
    #pragma unroll
    for (int j = 0; j < HID; j++) acc[j] = 0.0f;

    #pragma unroll
    for (int c = 0; c < 4; c++) {
        float4 xv[4];
        #pragma unroll
        for (int q = 0; q < 4; q++) xv[q] = __ldg(xr + c * 4 + q);
        const float* xs = (const float*)xv;
        #pragma unroll
        for (int kk = 0; kk < 16; kk++) {
            int k = c * 16 + kk;
            float xk = xs[kk];
            const float4* wr = (const float4*)&sW[k * HID];
            #pragma unroll
            for (int q = 0; q < 5; q++) {
                float4 wv = wr[q];
                acc[4 * q + 0] += xk * wv.x;
                acc[4 * q + 1] += xk * wv.y;
                acc[4 * q + 2] += xk * wv.z;
                acc[4 * q + 3] += xk * wv.w;
            }
        }
    }
    unsigned hp[16];
    #pragma unroll
    for (int q = 0; q < 10; q++) {
        __half2 h = __floats2half2_rn(acc[2 * q], acc[2 * q + 1]);
        hp[q] = *(unsigned*)&h;
    }
    #pragma unroll
    for (int q = 10; q < 16; q++) hp[q] = 0u;
    uint4* op = (uint4*)(g_bufA + (size_t)n * ROWH);
    op[0] = make_uint4(hp[0], hp[1], hp[2], hp[3]);
    op[1] = make_uint4(hp[4], hp[5], hp[6], hp[7]);
    op[2] = make_uint4(hp[8], hp[9], hp[10], hp[11]);
    op[3] = make_uint4(hp[12], hp[13], hp[14], hp[15]);
}

// ---------------- layer-1 aggregation (fp16 rows, 3-lane groups) ------------
#define AW 8
__global__ __launch_bounds__(AW * 32) void k_agg_h() {
    __shared__ float red[AW][32][9];
    int tid = threadIdx.x;
    int wid = tid >> 5, lane = tid & 31;
    int n = blockIdx.x * AW + wid;
    if (n >= N_NODES) return;

    const char* in = (const char*)g_bufA;
    bool uni = (g_wuni != 0);
    int rs = __ldg(&g_rowptr[n]);
    int re = __ldg(&g_rowptr[n + 1]);

    int grp  = lane / 3;
    int role = lane - grp * 3;
    bool active = grp < 10;

    float acc[8];
    #pragma unroll
    for (int j = 0; j < 8; j++) acc[j] = 0.0f;

    if (active) {
        if (uni) {
            const int* ep = g_edge_raw;
            for (int e = rs + grp; e < re; e += 10) {
                int s = __ldg(ep + e);
                uint4 v = __ldg((const uint4*)(in + (size_t)s * 64) + role);
                unsigned hp[4] = {v.x, v.y, v.z, v.w};
                #pragma unroll
                for (int q = 0; q < 4; q++) {
                    float2 f = __half22float2(*(__half2*)&hp[q]);
                    acc[2 * q + 0] += f.x;
                    acc[2 * q + 1] += f.y;
                }
            }
        } else {
            const int2* ep = (const int2*)g_edge_raw;
            for (int e = rs + grp; e < re; e += 10) {
                int2 p = __ldg(ep + e);
                float w = __int_as_float(p.y);
                uint4 v = __ldg((const uint4*)(in + (size_t)p.x * 64) + role);
                unsigned hp[4] = {v.x, v.y, v.z, v.w};
                #pragma unroll
                for (int q = 0; q < 4; q++) {
                    float2 f = __half22float2(*(__half2*)&hp[q]);
                    acc[2 * q + 0] += f.x * w;
                    acc[2 * q + 1] += f.y * w;
                }
            }
        }
    }

    float (*rp)[9] = red[wid];
    #pragma unroll
    for (int j = 0; j < 8; j++) rp[lane][j] = acc[j];
    __syncwarp();

    if (lane < HID) {
        int r = lane >> 3, j = lane & 7;
        float s = 0.0f;
        #pragma unroll
        for (int g = 0; g < 10; g++) s += rp[3 * g + r][j];
        g_agg[(size_t)n * HID + lane] = s;
    }
}

// ---------------- layers 2/3 aggregation (12-bit rows, 2-lane groups) -------
// 32B row = 1 L2 sector -> 1 wavefront/edge, 32B/edge (half the fp16 traffic).
// Row layout: two 128-bit halves; half r holds features r*10..r*10+9, each
// 12 bits (biased by 2048), packed little-endian from bit 0.
__global__ __launch_bounds__(AW * 32) void k_agg_q(int sel) {
    __shared__ float red[AW][32][11];
    int tid = threadIdx.x;
    int wid = tid >> 5, lane = tid & 31;
    int n = blockIdx.x * AW + wid;
    if (n >= N_NODES) return;

    const unsigned* in = sel ? g_bufQ2 : g_bufQ1;
    float step = g_qstep[sel];
    bool uni = (g_wuni != 0);
    int rs = __ldg(&g_rowptr[n]);
    int re = __ldg(&g_rowptr[n + 1]);

    int grp  = lane >> 1;          // 0..15
    int role = lane & 1;           // 0..1

    float acc[10];
    #pragma unroll
    for (int j = 0; j < 10; j++) acc[j] = 0.0f;

    if (uni) {
        const int* ep = g_edge_raw;
        for (int e = rs + grp; e < re; e += 16) {
            int s = __ldg(ep + e);
            uint4 v = __ldg((const uint4*)(in + (size_t)s * QW) + role);
            unsigned b[4] = {v.x, v.y, v.z, v.w};
            #pragma unroll
            for (int k = 0; k < 10; k++) {
                int bit = 12 * k, w = bit >> 5, off = bit & 31;
                unsigned raw = b[w] >> off;
                if (off + 12 > 32) raw |= b[w + 1] << (32 - off);
                raw &= 0xFFFu;
                acc[k] += (float)((int)raw - 2048);
            }
        }
    } else {
        const int2* ep = (const int2*)g_edge_raw;
        for (int e = rs + grp; e < re; e += 16) {
            int2 p = __ldg(ep + e);
            float we = __int_as_float(p.y);
            uint4 v = __ldg((const uint4*)(in + (size_t)p.x * QW) + role);
            unsigned b[4] = {v.x, v.y, v.z, v.w};
            #pragma unroll
            for (int k = 0; k < 10; k++) {
                int bit = 12 * k, w = bit >> 5, off = bit & 31;
                unsigned raw = b[w] >> off;
                if (off + 12 > 32) raw |= b[w + 1] << (32 - off);
                raw &= 0xFFFu;
                acc[k] += (float)((int)raw - 2048) * we;
            }
        }
    }

    float (*rp)[11] = red[wid];
    #pragma unroll
    for (int j = 0; j < 10; j++) rp[lane][j] = acc[j];
    __syncwarp();

    if (lane < HID) {
        int r = lane / 10, j = lane % 10;   // feature -> (role, slot)
        float s = 0.0f;
        #pragma unroll
        for (int g = 0; g < 16; g++) s += rp[2 * g + r][j];
        g_agg[(size_t)n * HID + lane] = s * step;   // fold dequant step once
    }
}

// ---------------- node MLP --------------------------------------------------
// mode 0: quantize o=h@Wn into Q1 (step slot 0)
// mode 1: quantize into Q2 (slot 1)
// mode 2: fused pooling (no row output)
__global__ __launch_bounds__(128) void k_mlp(const float* __restrict__ ba,
                                             const float* __restrict__ Wb,
                                             const float* __restrict__ bb,
                                             const float* __restrict__ Wn,
                                             const void* __restrict__ batch_v,
                                             int mode) {
    __shared__ float sWb[HID * HID], sWn[HID * HID], sba[HID], sbb[HID];
    __shared__ float scn[HID];
    __shared__ float sB;
    int tid = threadIdx.x;
    for (int i = tid; i < HID * HID; i += 128) {
        sWb[i] = Wb[i];
        sWn[i] = Wn ? Wn[i] : 0.0f;
    }
    if (tid < HID) { sba[tid] = ba[tid]; sbb[tid] = bb[tid]; }
    __syncthreads();
    if (mode != 2) {
        // exact bound: |o_j| <= ||Wn col_j||_2 since ||h||_2 <= 1
        if (tid < HID) {
            float ss = 0.0f;
            #pragma unroll
            for (int k = 0; k < HID; k++) {
                float w = sWn[k * HID + tid];
                ss += w * w;
            }
            scn[tid] = sqrtf(ss);
        }
        __syncthreads();
        if (tid == 0) {
            float B = 0.0f;
            #pragma unroll
            for (int j = 0; j < HID; j++) B = fmaxf(B, scn[j]);
            sB = B;
            if (blockIdx.x == 0) g_qstep[mode] = B / 2047.0f;
        }
        __syncthreads();
    }

    int n = blockIdx.x * 128 + tid;
    bool valid = n < N_NODES;
    if (!valid && mode != 2) return;

    float z[HID];
    if (valid) {
        float4 t[5];
        const float4* ag = (const float4*)(g_agg + (size_t)n * HID);
        #pragma unroll
        for (int i = 0; i < 5; i++) t[i] = __ldg(ag + i);
        float* zt = (float*)t;

        #pragma unroll
        for (int k = 0; k < HID; k++) z[k] = fmaxf(zt[k] + sba[k], 0.0f);

        float z2[HID];
        #pragma unroll
        for (int j = 0; j < HID; j++) {
            float a = sbb[j];
            #pragma unroll
            for (int k = 0; k < HID; k++) a += z[k] * sWb[k * HID + j];
            z2[j] = fmaxf(a, 0.0f);
        }

        float ss = 0.0f;
        #pragma unroll
        for (int k = 0; k < HID; k++) ss += z2[k] * z2[k];
        float inv = 1.0f / fmaxf(sqrtf(ss), EPS_NORM);
        #pragma unroll
        for (int k = 0; k < HID; k++) z[k] = fmaxf(z2[k] * inv, 0.0f);  // h
    } else {
        #pragma unroll
        for (int k = 0; k < HID; k++) z[k] = 0.0f;
    }

    if (mode != 2) {
        float o[HID];
        #pragma unroll
        for (int j = 0; j < HID; j++) {
            float a = 0.0f;
            #pragma unroll
            for (int k = 0; k < HID; k++) a += z[k] * sWn[k * HID + j];
            o[j] = a;
        }
        // quantize: 12-bit biased, two 128-bit halves of 10 features each
        float invq = (sB > 0.0f) ? (2047.0f / sB) : 0.0f;
        unsigned rowq[8] = {0, 0, 0, 0, 0, 0, 0, 0};
        #pragma unroll
        for (int h = 0; h < 2; h++) {
            #pragma unroll
            for (int k = 0; k < 10; k++) {
                int q = __float2int_rn(o[h * 10 + k] * invq) + 2048;
                q = max(0, min(4095, q));
                int bit = 12 * k, w = bit >> 5, off = bit & 31;
                rowq[4 * h + w] |= (unsigned)q << off;
                if (off + 12 > 32) rowq[4 * h + w + 1] |= (unsigned)q >> (32 - off);
            }
        }
        unsigned* base = (mode == 0) ? g_bufQ1 : g_bufQ2;
        uint4* op = (uint4*)(base + (size_t)n * QW);
        op[0] = make_uint4(rowq[0], rowq[1], rowq[2], rowq[3]);
        op[1] = make_uint4(rowq[4], rowq[5], rowq[6], rowq[7]);
        return;
    }

    // ---- fused global max/mean pooling (batch is sorted by graph) ----
    int g = -1;
    if (valid) {
        if (g_is64) g = (int)((const long long*)batch_v)[n];
        else        g = ((const int*)batch_v)[n];
    }
    const unsigned m = 0xffffffffu;
    int g0 = __shfl_sync(m, g, 0);
    bool uni = __all_sync(m, g == g0) && (g0 >= 0);
    int lane = tid & 31;

    if (uni) {
        #pragma unroll
        for (int f = 0; f < HID; f++) {
            float s = z[f], mx = z[f];
            #pragma unroll
            for (int off = 16; off > 0; off >>= 1) {
                s += __shfl_xor_sync(m, s, off);
                mx = fmaxf(mx, __shfl_xor_sync(m, mx, off));
            }
            if (lane == 0) {
                atomicAdd(&g_psum[g0 * HID + f], s);
                atomicMax((int*)&g_pmax[g0 * HID + f], __float_as_int(mx));  // h >= 0
            }
        }
        if (lane == 0) atomicAdd(&g_cnt[g0], 32.0f);
    } else if (valid) {
        #pragma unroll
        for (int f = 0; f < HID; f++) {
            atomicAdd(&g_psum[g * HID + f], z[f]);
            atomicMax((int*)&g_pmax[g * HID + f], __float_as_int(z[f]));
        }
        atomicAdd(&g_cnt[g], 1.0f);
    }
}

__global__ void k_final(const float* __restrict__ Wlin, const float* __restrict__ blin,
                        float* __restrict__ out) {
    int idx = blockIdx.x * blockDim.x + threadIdx.x;
    if (idx >= N_GRAPHS * N_CLASSES) return;
    int gph = idx / N_CLASSES, c = idx % N_CLASSES;
    float cnt = g_cnt[gph];
    float icnt = 1.0f / fmaxf(cnt, 1.0f);
    float acc = __ldg(blin + c);
    #pragma unroll
    for (int k = 0; k < HID; k++) {
        float mx = (cnt > 0.0f) ? g_pmax[gph * HID + k] : 0.0f;
        float mean = g_psum[gph * HID + k] * icnt;
        acc += mx * __ldg(Wlin + k * N_CLASSES + c)
             + mean * __ldg(Wlin + (HID + k) * N_CLASSES + c);
    }
    out[idx] = acc;
}

// ---------------- launch ----------------------------------------------------
extern "C" void kernel_launch(void* const* d_in, const int* in_sizes, int n_in,
                              void* d_out, int out_size) {
    const float* x    = (const float*)d_in[0];
    const void*  ei   = d_in[1];
    const void*  batch= d_in[2];
    const float* ew   = (const float*)d_in[3];
    const float* W1a  = (const float*)d_in[4];
    const float* b1a  = (const float*)d_in[5];
    const float* W1b  = (const float*)d_in[6];
    const float* b1b  = (const float*)d_in[7];
    const float* W2a  = (const float*)d_in[8];
    const float* b2a  = (const float*)d_in[9];
    const float* W2b  = (const float*)d_in[10];
    const float* b2b  = (const float*)d_in[11];
    const float* W3a  = (const float*)d_in[12];
    const float* b3a  = (const float*)d_in[13];
    const float* W3b  = (const float*)d_in[14];
    const float* b3b  = (const float*)d_in[15];
    const float* Wlin = (const float*)d_in[16];
    const float* blin = (const float*)d_in[17];
    float* out = (float*)d_out;

    const int eg = (N_EDGES + 255) / 256;
    const int ng = (N_NODES + 255) / 256;
    const int ag = (N_NODES + AW - 1) / AW;
    const int mg = (N_NODES + 127) / 128;
    const int gg = (N_NODES + 255) / 256;

    k_init<<<ng, 256>>>(ei);
    k_hist<<<eg, 256>>>(ei, ew);
    k_gemm_in<<<gg, 256>>>(x, W1a);
    k_scan1<<<SCAN_B, 1024>>>();
    k_scan2<<<1, 32>>>();
    k_scan3<<<SCAN_B, 1024>>>();
    k_fill<<<eg, 256>>>(ei, ew);

    // layer 1: fp16 gather; layers 2/3: 12-bit single-sector gather
    k_agg_h<<<ag, AW * 32>>>();     k_mlp<<<mg, 128>>>(b1a, W1b, b1b, W2a, nullptr, 0);
    k_agg_q<<<ag, AW * 32>>>(0);    k_mlp<<<mg, 128>>>(b2a, W2b, b2b, W3a, nullptr, 1);
    k_agg_q<<<ag, AW * 32>>>(1);    k_mlp<<<mg, 128>>>(b3a, W3b, b3b, nullptr, batch, 2);

    k_final<<<2, 640>>>(Wlin, blin, out);
}

// round 17
// speedup vs baseline: 1.0765x; 1.0332x over previous
#include <cuda_runtime.h>
#include <cuda_fp16.h>
#include <cstdint>

#define N_NODES 100000
#define N_EDGES 3200000
#define F_IN 64
#define HID 20
#define ROWH 32                             // halves per padded row (64B)
#define N_GRAPHS 128
#define N_CLASSES 10
#define EPS_NORM 1e-12f
#define SCAN_B ((N_NODES + 1023) / 1024)    // 98

// ---------------- scratch (device globals) ---------------------------------
__device__ __align__(128) __half g_bufA[N_NODES * ROWH];  // fp16 rows, 64B stride
__device__ __align__(128) __half g_bufB[N_NODES * ROWH];
__device__ __align__(16) float g_agg[N_NODES * HID];
__device__ __align__(16) int g_edge_raw[2 * N_EDGES];     // int2 (s,w) or int (s)
__device__ int g_deg[N_NODES];
__device__ int g_rowptr[N_NODES + 1];
__device__ int g_cursor[N_NODES];
__device__ int g_bsum[SCAN_B];
__device__ int g_boff[SCAN_B];
__device__ int g_scnt;
__device__ int g_sflag;
__device__ float g_pmax[N_GRAPHS * HID];
__device__ float g_psum[N_GRAPHS * HID];
__device__ float g_cnt[N_GRAPHS];
__device__ int   g_is64;
__device__ int   g_wuni;                                  // 1 if all weights == 1.0f

// ---------------- init: dtype probe + zero deg/pool/scan state --------------
__global__ void k_init(const void* __restrict__ ei) {
    int i = blockIdx.x * blockDim.x + threadIdx.x;
    if (i == 0) {
        const long long* p = (const long long*)ei;
        bool ok = true;
        #pragma unroll
        for (int q = 0; q < 16; q++) {
            long long v = p[q];
            if (v < 0 || v >= (long long)N_NODES) ok = false;
        }
        g_is64 = ok ? 1 : 0;
        g_wuni = 1;
        g_scnt = 0;
        g_sflag = 0;
    }
    if (i < N_NODES) g_deg[i] = 0;
    if (i < N_GRAPHS * HID) { g_pmax[i] = 0.0f; g_psum[i] = 0.0f; }
    if (i < N_GRAPHS) g_cnt[i] = 0.0f;
}

// ---------------- fused layer-1 GEMM + degree histogram ---------------------
// Independent work: grid-strided hist over edges (mem/atomic heavy), then one
// node GEMM per thread (FMA heavy). Blocks interleave the two phases chip-wide.
__global__ __launch_bounds__(256) void k_gemm_hist(const float* __restrict__ x,
                                                   const float* __restrict__ W,
                                                   const void* __restrict__ ei,
                                                   const float* __restrict__ w) {
    __shared__ float sW[F_IN * HID];   // 5.1 KB
    int tid = threadIdx.x;
    for (int i = tid; i < F_IN * HID; i += 256) sW[i] = W[i];

    // --- histogram part ---
    int gsz = gridDim.x * 256;
    int gt = blockIdx.x * 256 + tid;
    bool is64 = (g_is64 != 0);
    bool wbad = false;
    for (int e = gt; e < N_EDGES; e += gsz) {
        int d;
        if (is64) d = (int)((const long long*)ei)[N_EDGES + e];
        else      d = ((const int*)ei)[N_EDGES + e];
        atomicAdd(&g_deg[d], 1);
        if (w[e] != 1.0f) wbad = true;
    }
    if (wbad) g_wuni = 0;   // benign race: all writers store 0

    __syncthreads();

    // --- GEMM part ---
    int n = blockIdx.x * 256 + tid;
    if (n >= N_NODES) return;

    const float4* xr = (const float4*)(x + (size_t)n * F_IN);

    float acc[HID];
    #pragma unroll
    for (int j = 0; j < HID; j++) acc[j] = 0.0f;

    #pragma unroll
    for (int c = 0; c < 4; c++) {
        float4 xv[4];
        #pragma unroll
        for (int q = 0; q < 4; q++) xv[q] = __ldg(xr + c * 4 + q);
        const float* xs = (const float*)xv;
        #pragma unroll
        for (int kk = 0; kk < 16; kk++) {
            int k = c * 16 + kk;
            float xk = xs[kk];
            const float4* wr = (const float4*)&sW[k * HID];
            #pragma unroll
            for (int q = 0; q < 5; q++) {
                float4 wv = wr[q];
                acc[4 * q + 0] += xk * wv.x;
                acc[4 * q + 1] += xk * wv.y;
                acc[4 * q + 2] += xk * wv.z;
                acc[4 * q + 3] += xk * wv.w;
            }
        }
    }
    unsigned hp[16];
    #pragma unroll
    for (int q = 0; q < 10; q++) {
        __half2 h = __floats2half2_rn(acc[2 * q], acc[2 * q + 1]);
        hp[q] = *(unsigned*)&h;
    }
    #pragma unroll
    for (int q = 10; q < 16; q++) hp[q] = 0u;
    uint4* op = (uint4*)(g_bufA + (size_t)n * ROWH);
    op[0] = make_uint4(hp[0], hp[1], hp[2], hp[3]);
    op[1] = make_uint4(hp[4], hp[5], hp[6], hp[7]);
    op[2] = make_uint4(hp[8], hp[9], hp[10], hp[11]);
    op[3] = make_uint4(hp[12], hp[13], hp[14], hp[15]);
}

// ---------------- single-kernel exclusive scan (98 blocks, all resident) ----
__global__ __launch_bounds__(1024) void k_scan() {
    __shared__ int s[1024];
    int t = threadIdx.x;
    int i = blockIdx.x * 1024 + t;
    int v = (i < N_NODES) ? g_deg[i] : 0;
    s[t] = v;
    __syncthreads();
    #pragma unroll
    for (int off = 1; off < 1024; off <<= 1) {
        int u = (t >= off) ? s[t - off] : 0;
        __syncthreads();
        s[t] += u;
        __syncthreads();
    }
    int incl = s[t];

    if (t == 1023) {
        g_bsum[blockIdx.x] = s[1023];
        __threadfence();
        int done = atomicAdd(&g_scnt, 1);
        if (done == gridDim.x - 1) {            // last arriver scans block sums
            int run = 0;
            for (int b = 0; b < SCAN_B; b++) {
                g_boff[b] = run;
                run += g_bsum[b];
            }
            g_rowptr[N_NODES] = run;
            __threadfence();
            atomicExch(&g_sflag, 1);
        }
    }
    if (t == 0) {
        while (atomicAdd(&g_sflag, 0) == 0) { }
    }
    __syncthreads();
    __threadfence();

    if (i < N_NODES) {
        int ex = incl - v + g_boff[blockIdx.x];
        g_rowptr[i] = ex;
        g_cursor[i] = ex;
    }
}

__global__ void k_fill(const void* __restrict__ ei, const float* __restrict__ w) {
    int e = blockIdx.x * blockDim.x + threadIdx.x;
    if (e >= N_EDGES) return;
    int s, d;
    if (g_is64) {
        const long long* p = (const long long*)ei;
        s = (int)p[e]; d = (int)p[N_EDGES + e];
    } else {
        const int* p = (const int*)ei;
        s = p[e]; d = p[N_EDGES + e];
    }
    int pos = atomicAdd(&g_cursor[d], 1);
    if (g_wuni) {
        g_edge_raw[pos] = s;                          // src only, 4B
    } else {
        ((int2*)g_edge_raw)[pos] = make_int2(s, __float_as_int(w[e]));
    }
}

// ---------------- helpers ---------------------------------------------------
__device__ __forceinline__ void store_row_fp16(__half* base, int n, const float* o) {
    unsigned hp[16];
    #pragma unroll
    for (int q = 0; q < 10; q++) {
        __half2 h = __floats2half2_rn(o[2 * q], o[2 * q + 1]);
        hp[q] = *(unsigned*)&h;
    }
    #pragma unroll
    for (int q = 10; q < 16; q++) hp[q] = 0u;
    uint4* op = (uint4*)(base + (size_t)n * ROWH);
    op[0] = make_uint4(hp[0], hp[1], hp[2], hp[3]);
    op[1] = make_uint4(hp[4], hp[5], hp[6], hp[7]);
    op[2] = make_uint4(hp[8], hp[9], hp[10], hp[11]);
    op[3] = make_uint4(hp[12], hp[13], hp[14], hp[15]);
}

// ---------------- aggregation: warp/node, 3-lane cooperative row gather -----
// 10 groups x 3 lanes; lane role r loads bytes [16r,16r+16) of the 64B-aligned
// row -> never crosses a 128B line. Lean kernel, no unroll (round-14 champion).
// mode selects input: 0,2 -> bufA ; 1 -> bufB.  Output: g_agg (fp32).
#define AW 8
__global__ __launch_bounds__(AW * 32) void k_agg(int mode) {
    __shared__ float red[AW][32][9];   // [warp][lane][8 feats + pad]
    int tid = threadIdx.x;
    int wid = tid >> 5, lane = tid & 31;
    int n = blockIdx.x * AW + wid;
    if (n >= N_NODES) return;

    const char* in = (const char*)((mode == 1) ? g_bufB : g_bufA);
    bool uni = (g_wuni != 0);
    int rs = __ldg(&g_rowptr[n]);
    int re = __ldg(&g_rowptr[n + 1]);

    int grp  = lane / 3;           // 0..9 valid; 10 for lanes 30,31
    int role = lane - grp * 3;     // 0..2
    bool active = grp < 10;

    float acc[8];
    #pragma unroll
    for (int j = 0; j < 8; j++) acc[j] = 0.0f;

    if (active) {
        if (uni) {
            const int* ep = g_edge_raw;
            for (int e = rs + grp; e < re; e += 10) {
                int s = __ldg(ep + e);                       // broadcast within group
                uint4 v = __ldg((const uint4*)(in + (size_t)s * 64) + role);
                unsigned hp[4] = {v.x, v.y, v.z, v.w};
                #pragma unroll
                for (int q = 0; q < 4; q++) {
                    float2 f = __half22float2(*(__half2*)&hp[q]);
                    acc[2 * q + 0] += f.x;
                    acc[2 * q + 1] += f.y;
                }
            }
        } else {
            const int2* ep = (const int2*)g_edge_raw;
            for (int e = rs + grp; e < re; e += 10) {
                int2 p = __ldg(ep + e);
                float w = __int_as_float(p.y);
                uint4 v = __ldg((const uint4*)(in + (size_t)p.x * 64) + role);
                unsigned hp[4] = {v.x, v.y, v.z, v.w};
                #pragma unroll
                for (int q = 0; q < 4; q++) {
                    float2 f = __half22float2(*(__half2*)&hp[q]);
                    acc[2 * q + 0] += f.x * w;
                    acc[2 * q + 1] += f.y * w;
                }
            }
        }
    }

    // reduction: feature f = 8*role + j lives in lanes {3g + role}, g = 0..9
    float (*rp)[9] = red[wid];
    #pragma unroll
    for (int j = 0; j < 8; j++) rp[lane][j] = acc[j];
    __syncwarp();

    if (lane < HID) {
        int r = lane >> 3, j = lane & 7;   // feature -> (role, slot)
        float s = 0.0f;
        #pragma unroll
        for (int g = 0; g < 10; g++) s += rp[3 * g + r][j];
        g_agg[(size_t)n * HID + lane] = s;               // coalesced 80B per warp
    }
}

// ---------------- node MLP; mode 2 fuses global pooling ---------------------
// mode: 0 -> bufB(fp16), 1 -> bufA(fp16), 2 -> pooled atomics (no row output)
__global__ __launch_bounds__(128) void k_mlp(const float* __restrict__ ba,
                                             const float* __restrict__ Wb,
                                             const float* __restrict__ bb,
                                             const float* __restrict__ Wn,
                                             const void* __restrict__ batch_v,
                                             int mode) {
    __shared__ float sWb[HID * HID], sWn[HID * HID], sba[HID], sbb[HID];
    int tid = threadIdx.x;
    for (int i = tid; i < HID * HID; i += 128) {
        sWb[i] = Wb[i];
        sWn[i] = Wn ? Wn[i] : 0.0f;
    }
    if (tid < HID) { sba[tid] = ba[tid]; sbb[tid] = bb[tid]; }
    __syncthreads();
    int n = blockIdx.x * 128 + tid;
    bool valid = n < N_NODES;
    if (!valid && mode != 2) return;

    float z[HID];
    if (valid) {
        float4 t[5];
        const float4* ag = (const float4*)(g_agg + (size_t)n * HID);
        #pragma unroll
        for (int i = 0; i < 5; i++) t[i] = __ldg(ag + i);
        float* zt = (float*)t;

        #pragma unroll
        for (int k = 0; k < HID; k++) z[k] = fmaxf(zt[k] + sba[k], 0.0f);

        float z2[HID];
        #pragma unroll
        for (int j = 0; j < HID; j++) {
            float a = sbb[j];
            #pragma unroll
            for (int k = 0; k < HID; k++) a += z[k] * sWb[k * HID + j];
            z2[j] = fmaxf(a, 0.0f);
        }

        float ss = 0.0f;
        #pragma unroll
        for (int k = 0; k < HID; k++) ss += z2[k] * z2[k];
        float inv = 1.0f / fmaxf(sqrtf(ss), EPS_NORM);
        #pragma unroll
        for (int k = 0; k < HID; k++) z[k] = fmaxf(z2[k] * inv, 0.0f);  // h
    } else {
        #pragma unroll
        for (int k = 0; k < HID; k++) z[k] = 0.0f;
    }

    if (mode != 2) {
        float o[HID];
        #pragma unroll
        for (int j = 0; j < HID; j++) {
            float a = 0.0f;
            #pragma unroll
            for (int k = 0; k < HID; k++) a += z[k] * sWn[k * HID + j];
            o[j] = a;
        }
        store_row_fp16((mode == 0) ? g_bufB : g_bufA, n, o);
        return;
    }

    // ---- fused global max/mean pooling (batch is sorted by graph) ----
    int g = -1;
    if (valid) {
        if (g_is64) g = (int)((const long long*)batch_v)[n];
        else        g = ((const int*)batch_v)[n];
    }
    const unsigned m = 0xffffffffu;
    int g0 = __shfl_sync(m, g, 0);
    bool uni = __all_sync(m, g == g0) && (g0 >= 0);
    int lane = tid & 31;

    if (uni) {
        #pragma unroll
        for (int f = 0; f < HID; f++) {
            float s = z[f], mx = z[f];
            #pragma unroll
            for (int off = 16; off > 0; off >>= 1) {
                s += __shfl_xor_sync(m, s, off);
                mx = fmaxf(mx, __shfl_xor_sync(m, mx, off));
            }
            if (lane == 0) {
                atomicAdd(&g_psum[g0 * HID + f], s);
                atomicMax((int*)&g_pmax[g0 * HID + f], __float_as_int(mx));  // h >= 0
            }
        }
        if (lane == 0) atomicAdd(&g_cnt[g0], 32.0f);
    } else if (valid) {
        #pragma unroll
        for (int f = 0; f < HID; f++) {
            atomicAdd(&g_psum[g * HID + f], z[f]);
            atomicMax((int*)&g_pmax[g * HID + f], __float_as_int(z[f]));
        }
        atomicAdd(&g_cnt[g], 1.0f);
    }
}

__global__ void k_final(const float* __restrict__ Wlin, const float* __restrict__ blin,
                        float* __restrict__ out) {
    int idx = blockIdx.x * blockDim.x + threadIdx.x;
    if (idx >= N_GRAPHS * N_CLASSES) return;
    int gph = idx / N_CLASSES, c = idx % N_CLASSES;
    float cnt = g_cnt[gph];
    float icnt = 1.0f / fmaxf(cnt, 1.0f);
    float acc = __ldg(blin + c);
    #pragma unroll
    for (int k = 0; k < HID; k++) {
        float mx = (cnt > 0.0f) ? g_pmax[gph * HID + k] : 0.0f;
        float mean = g_psum[gph * HID + k] * icnt;
        acc += mx * __ldg(Wlin + k * N_CLASSES + c)
             + mean * __ldg(Wlin + (HID + k) * N_CLASSES + c);
    }
    out[idx] = acc;
}

// ---------------- launch ----------------------------------------------------
extern "C" void kernel_launch(void* const* d_in, const int* in_sizes, int n_in,
                              void* d_out, int out_size) {
    const float* x    = (const float*)d_in[0];
    const void*  ei   = d_in[1];
    const void*  batch= d_in[2];
    const float* ew   = (const float*)d_in[3];
    const float* W1a  = (const float*)d_in[4];
    const float* b1a  = (const float*)d_in[5];
    const float* W1b  = (const float*)d_in[6];
    const float* b1b  = (const float*)d_in[7];
    const float* W2a  = (const float*)d_in[8];
    const float* b2a  = (const float*)d_in[9];
    const float* W2b  = (const float*)d_in[10];
    const float* b2b  = (const float*)d_in[11];
    const float* W3a  = (const float*)d_in[12];
    const float* b3a  = (const float*)d_in[13];
    const float* W3b  = (const float*)d_in[14];
    const float* b3b  = (const float*)d_in[15];
    const float* Wlin = (const float*)d_in[16];
    const float* blin = (const float*)d_in[17];
    float* out = (float*)d_out;

    const int eg = (N_EDGES + 255) / 256;
    const int ng = (N_NODES + 255) / 256;
    const int ag = (N_NODES + AW - 1) / AW;
    const int mg = (N_NODES + 127) / 128;
    const int gg = (N_NODES + 255) / 256;

    k_init<<<ng, 256>>>(ei);
    k_gemm_hist<<<gg, 256>>>(x, W1a, ei, ew);
    k_scan<<<SCAN_B, 1024>>>();
    k_fill<<<eg, 256>>>(ei, ew);

    // three layers: lean agg (round-14 champion) + node MLP; layer 3 fuses pooling
    k_agg<<<ag, AW * 32>>>(0);  k_mlp<<<mg, 128>>>(b1a, W1b, b1b, W2a, nullptr, 0);
    k_agg<<<ag, AW * 32>>>(1);  k_mlp<<<mg, 128>>>(b2a, W2b, b2b, W3a, nullptr, 1);
    k_agg<<<ag, AW * 32>>>(2);  k_mlp<<<mg, 128>>>(b3a, W3b, b3b, nullptr, batch, 2);

    k_final<<<2, 640>>>(Wlin, blin, out);
}